// round 1
// baseline (speedup 1.0000x reference)
#include <cuda_runtime.h>

// ---------------------------------------------------------------------------
// 2-layer LSTM, B=2048, T=2048, I=1, H=16.
// One warp per batch element. Weights register-resident, packed for
// fma.rn.f32x2. Hidden state broadcast per step through a 64B SMEM region.
// ---------------------------------------------------------------------------

static constexpr int B = 2048;
static constexpr int T = 2048;
static constexpr int H = 16;

#define L2E 1.4426950408889634f

static __device__ __forceinline__ unsigned long long fma2(unsigned long long a,
                                                          unsigned long long b,
                                                          unsigned long long c) {
    unsigned long long d;
    asm("fma.rn.f32x2 %0, %1, %2, %3;" : "=l"(d) : "l"(a), "l"(b), "l"(c));
    return d;
}
static __device__ __forceinline__ unsigned long long pk2(float a, float b) {
    unsigned long long r;
    asm("mov.b64 %0, {%1, %2};" : "=l"(r) : "f"(a), "f"(b));
    return r;
}
static __device__ __forceinline__ void unpk2(unsigned long long v, float& a, float& b) {
    asm("mov.b64 {%0, %1}, %2;" : "=f"(a), "=f"(b) : "l"(v));
}
static __device__ __forceinline__ float ex2f_(float x) {
    float r; asm("ex2.approx.f32 %0, %1;" : "=f"(r) : "f"(x)); return r;
}
static __device__ __forceinline__ float rcpf_(float x) {
    float r; asm("rcp.approx.f32 %0, %1;" : "=f"(r) : "f"(x)); return r;
}
// sigmoid(x) = 1/(1+2^(-x*log2e))
static __device__ __forceinline__ float sig_(float x) {
    return rcpf_(1.0f + ex2f_(x * (-L2E)));
}
// tanh(x) = 2*sigmoid(2x)-1
static __device__ __forceinline__ float tanh_(float x) {
    return fmaf(2.0f, rcpf_(1.0f + ex2f_(x * (-2.0f * L2E))), -1.0f);
}

__global__ __launch_bounds__(64, 7)
void lstm2_kernel(const float* __restrict__ x,
                  const float* __restrict__ h0in,
                  const float* __restrict__ c0in,
                  const float* __restrict__ Wih0,
                  const float* __restrict__ Whh0,
                  const float* __restrict__ bih0,
                  const float* __restrict__ bhh0,
                  const float* __restrict__ Wih1,
                  const float* __restrict__ Whh1,
                  const float* __restrict__ bih1,
                  const float* __restrict__ bhh1,
                  float* __restrict__ out)
{
    // per-CTA: 2 warps, each warp owns [layer0 h (16f), layer1 h (16f)]
    __shared__ __align__(16) float smh[2][2][16];

    const int tid  = threadIdx.x;
    const int wid  = tid >> 5;
    const int lane = tid & 31;
    const int j    = lane & 15;       // hidden unit
    const int half = lane >> 4;       // 0: gates (i,f)[j], 1: gates (g,o)[j]
    const int b    = blockIdx.x * 2 + wid;

    const int gA = half * 32 + j;     // i[j] or g[j]
    const int gB = gA + 16;           // f[j] or o[j]

    // ---- load weights into registers, packed over k-pairs (f32x2) ----
    unsigned long long w0A[8], w0B[8], wiA[8], wiB[8], w1A[8], w1B[8];
    const float2* Wh0v = reinterpret_cast<const float2*>(Whh0);
    const float2* Wi1v = reinterpret_cast<const float2*>(Wih1);
    const float2* Wh1v = reinterpret_cast<const float2*>(Whh1);
#pragma unroll
    for (int p = 0; p < 8; ++p) {
        float2 a  = Wh0v[gA * 8 + p]; w0A[p] = pk2(a.x, a.y);
        float2 b2 = Wh0v[gB * 8 + p]; w0B[p] = pk2(b2.x, b2.y);
        float2 c  = Wi1v[gA * 8 + p]; wiA[p] = pk2(c.x, c.y);
        float2 d  = Wi1v[gB * 8 + p]; wiB[p] = pk2(d.x, d.y);
        float2 e  = Wh1v[gA * 8 + p]; w1A[p] = pk2(e.x, e.y);
        float2 f  = Wh1v[gB * 8 + p]; w1B[p] = pk2(f.x, f.y);
    }
    const float biasA0 = bih0[gA] + bhh0[gA];
    const float biasB0 = bih0[gB] + bhh0[gB];
    const float biasA1 = bih1[gA] + bhh1[gA];
    const float biasB1 = bih1[gB] + bhh1[gB];
    const float wxA = Wih0[gA];   // I == 1
    const float wxB = Wih0[gB];

    // activation params for scalar A (half0: sigmoid, half1: tanh)
    const float kA = half ? (-2.0f * L2E) : (-L2E);
    const float mA = half ? 2.0f : 1.0f;
    const float cAc = half ? -1.0f : 0.0f;

    // ---- initial state (only half==0 lanes hold authoritative copies) ----
    float c0v = c0in[b * H + j];
    float c1v = c0in[B * H + b * H + j];
    float h0v = h0in[b * H + j];
    float h1v = h0in[B * H + b * H + j];

    float* h0s = smh[wid][0];
    float* h1s = smh[wid][1];
    if (!half) { h0s[j] = h0v; h1s[j] = h1v; }
    __syncwarp();

    const float* xrow = x + (size_t)b * T;
    float*       orow = out + (size_t)b * T * H + j;

    float xv = __ldg(xrow);

    for (int t = 0; t < T; ++t) {
        // prefetch next x
        const int tn = (t + 1 < T) ? (t + 1) : (T - 1);
        const float xn = __ldg(xrow + tn);

        // ================= layer 0: gates = Whh0 @ h0 + x*Wih0 + bias ======
        {
            const ulonglong2* hp = reinterpret_cast<const ulonglong2*>(h0s);
            ulonglong2 u0 = hp[0], u1 = hp[1], u2 = hp[2], u3 = hp[3];
            unsigned long long accA = 0ull, accB = 0ull;
            accA = fma2(w0A[0], u0.x, accA);  accB = fma2(w0B[0], u0.x, accB);
            accA = fma2(w0A[1], u0.y, accA);  accB = fma2(w0B[1], u0.y, accB);
            accA = fma2(w0A[2], u1.x, accA);  accB = fma2(w0B[2], u1.x, accB);
            accA = fma2(w0A[3], u1.y, accA);  accB = fma2(w0B[3], u1.y, accB);
            accA = fma2(w0A[4], u2.x, accA);  accB = fma2(w0B[4], u2.x, accB);
            accA = fma2(w0A[5], u2.y, accA);  accB = fma2(w0B[5], u2.y, accB);
            accA = fma2(w0A[6], u3.x, accA);  accB = fma2(w0B[6], u3.x, accB);
            accA = fma2(w0A[7], u3.y, accA);  accB = fma2(w0B[7], u3.y, accB);

            float aL, aH, bL, bH;
            unpk2(accA, aL, aH);
            unpk2(accB, bL, bH);
            const float gAraw = (aL + aH) + fmaf(xv, wxA, biasA0);
            const float gBraw = (bL + bH) + fmaf(xv, wxB, biasB0);

            // activations: A -> sigmoid(i) / tanh(g); B -> sigmoid(f) / sigmoid(o)
            const float sA = fmaf(mA, rcpf_(1.0f + ex2f_(gAraw * kA)), cAc);
            const float sB = sig_(gBraw);

            // exchange: half0 receives (g, o)
            const float gg = __shfl_xor_sync(0xffffffffu, sA, 16);
            const float oo = __shfl_xor_sync(0xffffffffu, sB, 16);
            c0v = fmaf(sB, c0v, sA * gg);     // valid on half0 only
            h0v = oo * tanh_(c0v);            // valid on half0 only
            if (!half) h0s[j] = h0v;
        }
        __syncwarp();

        // ====== layer 1: gates = Wih1 @ h0_new + Whh1 @ h1 + bias ==========
        {
            const ulonglong2* hp0 = reinterpret_cast<const ulonglong2*>(h0s);
            const ulonglong2* hp1 = reinterpret_cast<const ulonglong2*>(h1s);
            ulonglong2 u0 = hp0[0], u1 = hp0[1], u2 = hp0[2], u3 = hp0[3];
            ulonglong2 v0 = hp1[0], v1 = hp1[1], v2 = hp1[2], v3 = hp1[3];
            unsigned long long accA = 0ull, accB = 0ull;
            accA = fma2(wiA[0], u0.x, accA);  accB = fma2(wiB[0], u0.x, accB);
            accA = fma2(wiA[1], u0.y, accA);  accB = fma2(wiB[1], u0.y, accB);
            accA = fma2(wiA[2], u1.x, accA);  accB = fma2(wiB[2], u1.x, accB);
            accA = fma2(wiA[3], u1.y, accA);  accB = fma2(wiB[3], u1.y, accB);
            accA = fma2(wiA[4], u2.x, accA);  accB = fma2(wiB[4], u2.x, accB);
            accA = fma2(wiA[5], u2.y, accA);  accB = fma2(wiB[5], u2.y, accB);
            accA = fma2(wiA[6], u3.x, accA);  accB = fma2(wiB[6], u3.x, accB);
            accA = fma2(wiA[7], u3.y, accA);  accB = fma2(wiB[7], u3.y, accB);

            accA = fma2(w1A[0], v0.x, accA);  accB = fma2(w1B[0], v0.x, accB);
            accA = fma2(w1A[1], v0.y, accA);  accB = fma2(w1B[1], v0.y, accB);
            accA = fma2(w1A[2], v1.x, accA);  accB = fma2(w1B[2], v1.x, accB);
            accA = fma2(w1A[3], v1.y, accA);  accB = fma2(w1B[3], v1.y, accB);
            accA = fma2(w1A[4], v2.x, accA);  accB = fma2(w1B[4], v2.x, accB);
            accA = fma2(w1A[5], v2.y, accA);  accB = fma2(w1B[5], v2.y, accB);
            accA = fma2(w1A[6], v3.x, accA);  accB = fma2(w1B[6], v3.x, accB);
            accA = fma2(w1A[7], v3.y, accA);  accB = fma2(w1B[7], v3.y, accB);

            float aL, aH, bL, bH;
            unpk2(accA, aL, aH);
            unpk2(accB, bL, bH);
            const float gAraw = (aL + aH) + biasA1;
            const float gBraw = (bL + bH) + biasB1;

            const float sA = fmaf(mA, rcpf_(1.0f + ex2f_(gAraw * kA)), cAc);
            const float sB = sig_(gBraw);

            const float gg = __shfl_xor_sync(0xffffffffu, sA, 16);
            const float oo = __shfl_xor_sync(0xffffffffu, sB, 16);
            c1v = fmaf(sB, c1v, sA * gg);
            h1v = oo * tanh_(c1v);
            if (!half) {
                h1s[j] = h1v;
                orow[(size_t)t * H] = h1v;   // out1[b, t, j]
            }
        }
        xv = xn;
        __syncwarp();
    }

    // final states: hN [2,B,H] then cN [2,B,H] appended after out1 [B,T,H]
    if (!half) {
        float* hN = out + (size_t)B * T * H;
        float* cN = hN + 2 * B * H;
        hN[b * H + j]         = h0v;
        hN[B * H + b * H + j] = h1v;
        cN[b * H + j]         = c0v;
        cN[B * H + b * H + j] = c1v;
    }
}

extern "C" void kernel_launch(void* const* d_in, const int* in_sizes, int n_in,
                              void* d_out, int out_size) {
    const float* x    = (const float*)d_in[0];
    const float* h0   = (const float*)d_in[1];
    const float* c0   = (const float*)d_in[2];
    const float* Wih0 = (const float*)d_in[3];
    const float* Whh0 = (const float*)d_in[4];
    const float* bih0 = (const float*)d_in[5];
    const float* bhh0 = (const float*)d_in[6];
    const float* Wih1 = (const float*)d_in[7];
    const float* Whh1 = (const float*)d_in[8];
    const float* bih1 = (const float*)d_in[9];
    const float* bhh1 = (const float*)d_in[10];
    float* out = (float*)d_out;

    lstm2_kernel<<<B / 2, 64>>>(x, h0, c0, Wih0, Whh0, bih0, bhh0,
                                Wih1, Whh1, bih1, bhh1, out);
}